// round 13
// baseline (speedup 1.0000x reference)
#include <cuda_runtime.h>
#include <cuda_fp16.h>
#include <cstdint>
#include <math.h>

#define B_    2
#define S_    4096
#define D_    512
#define H_    8
#define HD_   64
#define ROWS_ (B_*S_)   // 8192

// fp16 scratch
__device__ __half g_xh   [(size_t)ROWS_*D_];
__device__ __half g_wqkvh[(size_t)3*D_*D_];
__device__ __half g_wch  [(size_t)D_*D_];
__device__ __half g_qh   [(size_t)B_*H_*S_*HD_];
__device__ __half g_kh   [(size_t)B_*H_*S_*HD_];
__device__ __half g_vh   [(size_t)B_*H_*S_*HD_];
__device__ __half g_atth [(size_t)B_*S_*D_];

__device__ __forceinline__ float ex2f(float x) {
    float r; asm("ex2.approx.ftz.f32 %0, %1;" : "=f"(r) : "f"(x)); return r;
}
__device__ __forceinline__ uint32_t smem_u32(const void* p) {
    uint32_t a;
    asm("{ .reg .u64 t; cvta.to.shared.u64 t, %1; cvt.u32.u64 %0, t; }" : "=r"(a) : "l"(p));
    return a;
}
__device__ __forceinline__ void mma16816(float* d, const uint32_t* a,
                                         const uint32_t* b, const float* c) {
    asm volatile(
        "mma.sync.aligned.m16n8k16.row.col.f32.f16.f16.f32 "
        "{%0,%1,%2,%3}, {%4,%5,%6,%7}, {%8,%9}, {%10,%11,%12,%13};"
        : "=f"(d[0]), "=f"(d[1]), "=f"(d[2]), "=f"(d[3])
        : "r"(a[0]), "r"(a[1]), "r"(a[2]), "r"(a[3]),
          "r"(b[0]), "r"(b[1]),
          "f"(c[0]), "f"(c[1]), "f"(c[2]), "f"(c[3]));
}
__device__ __forceinline__ uint32_t pack_half2(float a, float b) {
    __half2 h = __floats2half2_rn(a, b);
    return *(uint32_t*)&h;
}

#define CP16(sa, gp) asm volatile("cp.async.cg.shared.global [%0], [%1], 16;" :: "r"(sa), "l"(gp))
#define CP_COMMIT()  asm volatile("cp.async.commit_group;")
#define CP_WAIT0()   asm volatile("cp.async.wait_group 0;")
#define BAR(id, cnt) asm volatile("bar.sync %0, %1;" :: "r"(id), "r"(cnt) : "memory")

#define LDSM4(r0,r1,r2,r3,a) \
    asm volatile("ldmatrix.sync.aligned.m8n8.x4.shared.b16 {%0,%1,%2,%3}, [%4];" \
        : "=r"(r0),"=r"(r1),"=r"(r2),"=r"(r3) : "r"(a))
#define LDSM4T(r0,r1,r2,r3,a) \
    asm volatile("ldmatrix.sync.aligned.m8n8.x4.trans.shared.b16 {%0,%1,%2,%3}, [%4];" \
        : "=r"(r0),"=r"(r1),"=r"(r2),"=r"(r3) : "r"(a))

// ===========================================================================
// fp32 -> fp16 conversions
// ===========================================================================
__global__ void f2h_kernel(const float* __restrict__ src, __half* __restrict__ dst, int n) {
    int i = (blockIdx.x * blockDim.x + threadIdx.x) * 4;
    if (i < n) {
        float4 v = *(const float4*)(src + i);
        *(uint2*)(dst + i) = make_uint2(pack_half2(v.x, v.y), pack_half2(v.z, v.w));
    }
}
__global__ void f2h_w4_kernel(const float* __restrict__ wq, const float* __restrict__ wk,
                              const float* __restrict__ wv, const float* __restrict__ wc,
                              __half* __restrict__ wqkv, __half* __restrict__ wcd) {
    const int sel = blockIdx.x >> 8;
    const int i = ((blockIdx.x & 255) * blockDim.x + threadIdx.x) * 4;
    const float* src = sel == 0 ? wq : (sel == 1 ? wk : (sel == 2 ? wv : wc));
    __half* dst = sel == 3 ? wcd : (wqkv + (size_t)sel * D_ * D_);
    float4 v = *(const float4*)(src + i);
    *(uint2*)(dst + i) = make_uint2(pack_half2(v.x, v.y), pack_half2(v.z, v.w));
}

// ===========================================================================
// Pipelined fp16 HMMA GEMM (unchanged)
// ===========================================================================
#define PM 128
#define PN 64
#define PKC 64
#define PPAD 72

__global__ void __launch_bounds__(256) hgemm_kernel(
    const __half* __restrict__ A, const __half* __restrict__ Wh,
    __half* __restrict__ qh, __half* __restrict__ kh, __half* __restrict__ vh,
    float* __restrict__ outF, const float* __restrict__ bias, float qscale) {
    __shared__ __half As[2][PM][PPAD];
    __shared__ __half Bs[2][PN][PPAD];
    const int tid = threadIdx.x;
    const int w = tid >> 5, lane = tid & 31;
    const int l4 = lane >> 2, cq = (lane & 3) * 2;
    const int bm0 = blockIdx.y * PM, bn0 = blockIdx.x * PN;
    const int mrow = (w >> 1) * 32, ncol = (w & 1) * 32;

    const uint32_t sbA = smem_u32(&As[0][0][0]);
    const uint32_t sbB = smem_u32(&Bs[0][0][0]);

    const int a_r = (lane & 7) + ((lane >> 3) & 1) * 8;
    const int a_c = (lane >> 4) * 8;
    const int b_r = lane & 7;
    const int b_c = (lane >> 3) * 8;

    auto loadAB = [&](int s, int kc) {
        #pragma unroll
        for (int i = 0; i < 4; i++) {
            int f = tid + i * 256;
            int r = f >> 3, c8 = f & 7;
            CP16(sbA + ((s * PM + r) * PPAD + c8 * 8) * 2,
                 A + (size_t)(bm0 + r) * D_ + kc * PKC + c8 * 8);
        }
        #pragma unroll
        for (int i = 0; i < 2; i++) {
            int f = tid + i * 256;
            int r = f >> 3, c8 = f & 7;
            CP16(sbB + ((s * PN + r) * PPAD + c8 * 8) * 2,
                 Wh + (size_t)(bn0 + r) * D_ + kc * PKC + c8 * 8);
        }
        CP_COMMIT();
    };

    float o[2][4][4];
    #pragma unroll
    for (int mt = 0; mt < 2; mt++)
        #pragma unroll
        for (int n = 0; n < 4; n++)
            #pragma unroll
            for (int j = 0; j < 4; j++) o[mt][n][j] = 0.f;

    loadAB(0, 0);

    const int NKC = D_ / PKC;
    for (int kc = 0; kc < NKC; kc++) {
        CP_WAIT0();
        __syncthreads();
        if (kc + 1 < NKC) loadAB((kc + 1) & 1, kc + 1);
        const int s = kc & 1;

        uint32_t af[2][4][4];
        #pragma unroll
        for (int mt = 0; mt < 2; mt++) {
            #pragma unroll
            for (int kk = 0; kk < 4; kk++) {
                uint32_t addr = sbA + ((s * PM + mrow + mt * 16 + a_r) * PPAD
                                       + kk * 16 + a_c) * 2;
                LDSM4(af[mt][kk][0], af[mt][kk][1], af[mt][kk][2], af[mt][kk][3], addr);
            }
        }
        #pragma unroll
        for (int n = 0; n < 4; n++) {
            uint32_t b0, b1, b2, b3, c0, c1, c2, c3;
            uint32_t addr = sbB + ((s * PN + ncol + n * 8 + b_r) * PPAD + b_c) * 2;
            LDSM4(b0, b1, b2, b3, addr);
            LDSM4(c0, c1, c2, c3, addr + 64);
            uint32_t bf0[2] = {b0, b1}, bf1[2] = {b2, b3};
            uint32_t bf2[2] = {c0, c1}, bf3[2] = {c2, c3};
            #pragma unroll
            for (int mt = 0; mt < 2; mt++) {
                mma16816(o[mt][n], af[mt][0], bf0, o[mt][n]);
                mma16816(o[mt][n], af[mt][1], bf1, o[mt][n]);
                mma16816(o[mt][n], af[mt][2], bf2, o[mt][n]);
                mma16816(o[mt][n], af[mt][3], bf3, o[mt][n]);
            }
        }
    }

    if (outF == nullptr) {
        const int sel = bn0 >> 9;
        __half* dst = sel == 0 ? qh : (sel == 1 ? kh : vh);
        const float sc = sel == 0 ? qscale : 1.f;
        #pragma unroll
        for (int mt = 0; mt < 2; mt++) {
            int r0 = bm0 + mrow + mt * 16 + l4;
            #pragma unroll
            for (int n = 0; n < 4; n++) {
                int cw = (bn0 + ncol + n * 8 + cq) & (D_ - 1);
                int h = cw >> 6, hd = cw & (HD_ - 1);
                #pragma unroll
                for (int rr = 0; rr < 2; rr++) {
                    int row = r0 + rr * 8;
                    int b = row >> 12, s2 = row & (S_ - 1);
                    uint32_t pv = pack_half2(o[mt][n][rr * 2] * sc,
                                             o[mt][n][rr * 2 + 1] * sc);
                    *(uint32_t*)&dst[((size_t)(b * H_ + h) * S_ + s2) * HD_ + hd] = pv;
                }
            }
        }
    } else {
        #pragma unroll
        for (int mt = 0; mt < 2; mt++) {
            int r0 = bm0 + mrow + mt * 16 + l4;
            #pragma unroll
            for (int n = 0; n < 4; n++) {
                int col = bn0 + ncol + n * 8 + cq;
                float b0 = bias[col], b1 = bias[col + 1];
                float* p0 = outF + (size_t)r0 * D_ + col;
                float* p1 = outF + (size_t)(r0 + 8) * D_ + col;
                p0[0] = o[mt][n][0] + b0; p0[1] = o[mt][n][1] + b1;
                p1[0] = o[mt][n][2] + b0; p1[1] = o[mt][n][3] + b1;
            }
        }
    }
}

// ===========================================================================
// Flash attention v5: 256-thread CTA, BQ=128, 32 rows/warp (mt=2).
// Groups A = warps 0-3 (even key tiles), B = warps 4-7 (odd key tiles):
// SMSP i holds warp i (A) AND warp i+4 (B) -> deterministic anti-phase pair
// sharing each tensor unit. Per-group 2-stage cp.async rings.
// ===========================================================================
#define BQ   128
#define BK   64
#define NT   (S_ / BK)          // 64 global tiles; 32 per group
#define NTL  (NT / 2)
#define QPAD 72
#define QS_H   (BQ * QPAD)              // 9216 halves
#define STG_H  (2 * BK * QPAD)          // 9216 halves (K + V)
#define KS_H(s) (QS_H + (s) * STG_H)    // stages 0..3 (A: 0,1  B: 2,3)
#define VS_H(s) (KS_H(s) + BK * QPAD)
#define MRG_H  KS_H(2)                  // merge buffer over group-B stages (36KB)
#define SM_HALVES (QS_H + 4 * STG_H)    // 46080 halves
#define SM_BYTES  (SM_HALVES * 2)       // 92160

__global__ void __launch_bounds__(256, 1) attn_hmma_kernel(
    const __half* __restrict__ Qg, const __half* __restrict__ Kg,
    const __half* __restrict__ Vg, __half* __restrict__ att) {
    extern __shared__ __half sm[];
    const uint32_t sb = smem_u32(sm);

    const int tid = threadIdx.x;
    const int w = tid >> 5, lane = tid & 31;
    const int g  = w >> 2;                // warp group 0/1 (SMSP-paired)
    const int wg = w & 3;                 // warp within group (row quarter)
    const int tl = tid & 127;             // thread within group
    const int l4 = lane >> 2;
    const int cq = (lane & 3) * 2;
    const int bh = blockIdx.y;
    const int q0 = blockIdx.x * BQ;

    const __half* Qp = Qg + ((size_t)bh * S_ + q0) * HD_;
    const __half* Kp = Kg + (size_t)bh * S_ * HD_;
    const __half* Vp = Vg + (size_t)bh * S_ * HD_;

    // issue K/V for global tile gt into stage s (group's 128 threads)
    auto issue_kv = [&](int gt, int s) {
        const __half* Kt = Kp + (size_t)gt * BK * HD_;
        const __half* Vt = Vp + (size_t)gt * BK * HD_;
        #pragma unroll
        for (int i = 0; i < 4; i++) {
            int f = tl + i * 128;
            int r = f >> 3, c8 = f & 7;
            CP16(sb + (KS_H(s) + r * QPAD + c8 * 8) * 2, Kt + (size_t)r * HD_ + c8 * 8);
            CP16(sb + (VS_H(s) + r * QPAD + c8 * 8) * 2, Vt + (size_t)r * HD_ + c8 * 8);
        }
        CP_COMMIT();
    };

    // ---- load Q tile: 128 rows x 8 chunks = 1024 chunks / 256 threads ----
    #pragma unroll
    for (int i = 0; i < 4; i++) {
        int f = tid + i * 256;
        int r = f >> 3, c8 = f & 7;
        *(uint4*)&sm[r * QPAD + c8 * 8] = *(const uint4*)(Qp + (size_t)r * HD_ + c8 * 8);
    }

    issue_kv(g, g * 2);
    __syncthreads();   // Q visible

    // ---- Q fragments: rows wg*32 + mt*16 (+l4, +8) ----
    uint32_t qa[2][4][4];
    #pragma unroll
    for (int mt = 0; mt < 2; mt++) {
        const int row = wg * 32 + mt * 16 + l4;
        #pragma unroll
        for (int kk = 0; kk < 4; kk++) {
            qa[mt][kk][0] = *(uint32_t*)&sm[(row    ) * QPAD + kk * 16 + cq];
            qa[mt][kk][1] = *(uint32_t*)&sm[(row + 8) * QPAD + kk * 16 + cq];
            qa[mt][kk][2] = *(uint32_t*)&sm[(row    ) * QPAD + kk * 16 + 8 + cq];
            qa[mt][kk][3] = *(uint32_t*)&sm[(row + 8) * QPAD + kk * 16 + 8 + cq];
        }
    }

    float o[2][8][4];
    float lsum[2][2];
    #pragma unroll
    for (int mt = 0; mt < 2; mt++) {
        lsum[mt][0] = 0.f; lsum[mt][1] = 0.f;
        #pragma unroll
        for (int n = 0; n < 8; n++)
            #pragma unroll
            for (int j = 0; j < 4; j++) o[mt][n][j] = 0.f;
    }

    const int k_row8 = lane & 7;
    const int k_hdb  = (lane >> 3) * 8;
    const int v_key  = ((lane >> 3) & 1) * 8 + (lane & 7);
    const int v_hdb  = (lane >> 4) * 8;
    const int bar_id = g + 1;

    for (int t = 0; t < NTL; t++) {
        CP_WAIT0();
        BAR(bar_id, 128);   // group's tile t arrived; all group warps past t-1

        if (t + 1 < NTL) issue_kv(2 * (t + 1) + g, g * 2 + ((t + 1) & 1));

        const uint32_t ks = sb + KS_H(g * 2 + (t & 1)) * 2;
        const uint32_t vs = sb + VS_H(g * 2 + (t & 1)) * 2;

        // ---- S = Q @ K^T  (32 x 64 per warp; K-frags reused across 2 m-tiles) ----
        float s[2][8][4];
        #pragma unroll
        for (int mt = 0; mt < 2; mt++)
            #pragma unroll
            for (int n = 0; n < 8; n++)
                #pragma unroll
                for (int j = 0; j < 4; j++) s[mt][n][j] = 0.f;

        #pragma unroll
        for (int n = 0; n < 8; n++) {
            uint32_t b0, b1, b2, b3, c0, c1, c2, c3;
            uint32_t a1 = ks + ((n * 8 + k_row8) * QPAD + k_hdb) * 2;
            LDSM4(b0, b1, b2, b3, a1);
            LDSM4(c0, c1, c2, c3, a1 + 64);
            uint32_t bk0[2] = {b0, b1}, bk1[2] = {b2, b3};
            uint32_t bk2[2] = {c0, c1}, bk3[2] = {c2, c3};
            #pragma unroll
            for (int mt = 0; mt < 2; mt++) {
                mma16816(s[mt][n], qa[mt][0], bk0, s[mt][n]);
                mma16816(s[mt][n], qa[mt][1], bk1, s[mt][n]);
                mma16816(s[mt][n], qa[mt][2], bk2, s[mt][n]);
                mma16816(s[mt][n], qa[mt][3], bk3, s[mt][n]);
            }
        }

        // ---- softmax (no max subtraction; Q pre-scaled by log2e/8) ----
        uint32_t pa[2][4][4];
        #pragma unroll
        for (int mt = 0; mt < 2; mt++) {
            #pragma unroll
            for (int n = 0; n < 8; n++) {
                float p0 = ex2f(s[mt][n][0]);
                float p1 = ex2f(s[mt][n][1]);
                float p2 = ex2f(s[mt][n][2]);
                float p3 = ex2f(s[mt][n][3]);
                lsum[mt][0] += p0 + p1;
                lsum[mt][1] += p2 + p3;
                int j = n >> 1;
                if ((n & 1) == 0) {
                    pa[mt][j][0] = pack_half2(p0, p1);
                    pa[mt][j][1] = pack_half2(p2, p3);
                } else {
                    pa[mt][j][2] = pack_half2(p0, p1);
                    pa[mt][j][3] = pack_half2(p2, p3);
                }
            }
        }

        // ---- O += P @ V  (V-frags reused across 2 m-tiles) ----
        #pragma unroll
        for (int np = 0; np < 4; np++) {
            #pragma unroll
            for (int j = 0; j < 4; j++) {
                uint32_t v0, v1, v2, v3;
                uint32_t av = vs + ((j * 16 + v_key) * QPAD + np * 16 + v_hdb) * 2;
                LDSM4T(v0, v1, v2, v3, av);
                uint32_t bv0[2] = {v0, v1}, bv1[2] = {v2, v3};
                #pragma unroll
                for (int mt = 0; mt < 2; mt++) {
                    mma16816(o[mt][2 * np],     pa[mt][j], bv0, o[mt][2 * np]);
                    mma16816(o[mt][2 * np + 1], pa[mt][j], bv1, o[mt][2 * np + 1]);
                }
            }
        }
    }

    // ---- merge group B partials into group A ----
    float* mo = (float*)(sm + MRG_H);              // [4 warps][32 lanes][64]
    float* ml = (float*)(sm);                       // lsum partials over Q area (done with Q)
    if (g == 1) {
        const int idx = wg * 32 + lane;            // 0..127
        #pragma unroll
        for (int mt = 0; mt < 2; mt++)
            #pragma unroll
            for (int n = 0; n < 8; n++)
                #pragma unroll
                for (int j = 0; j < 4; j++)
                    mo[idx * 64 + mt * 32 + n * 4 + j] = o[mt][n][j];
        #pragma unroll
        for (int mt = 0; mt < 2; mt++) {
            ml[idx * 4 + mt * 2]     = lsum[mt][0];
            ml[idx * 4 + mt * 2 + 1] = lsum[mt][1];
        }
    }
    __syncthreads();
    if (g == 0) {
        const int idx = wg * 32 + lane;
        #pragma unroll
        for (int mt = 0; mt < 2; mt++) {
            #pragma unroll
            for (int n = 0; n < 8; n++)
                #pragma unroll
                for (int j = 0; j < 4; j++)
                    o[mt][n][j] += mo[idx * 64 + mt * 32 + n * 4 + j];
            lsum[mt][0] += ml[idx * 4 + mt * 2];
            lsum[mt][1] += ml[idx * 4 + mt * 2 + 1];
        }

        #pragma unroll
        for (int mt = 0; mt < 2; mt++)
            #pragma unroll
            for (int hh = 0; hh < 2; hh++) {
                float v = lsum[mt][hh];
                v += __shfl_xor_sync(0xffffffffu, v, 1);
                v += __shfl_xor_sync(0xffffffffu, v, 2);
                lsum[mt][hh] = v;
            }

        const int b = bh >> 3, h = bh & 7;
        #pragma unroll
        for (int mt = 0; mt < 2; mt++) {
            const int row = q0 + wg * 32 + mt * 16 + l4;
            const float inv0 = 1.f / lsum[mt][0];
            const float inv1 = 1.f / lsum[mt][1];
            __half* op0 = att + ((size_t)(b * S_ + row    )) * D_ + h * HD_;
            __half* op1 = att + ((size_t)(b * S_ + row + 8)) * D_ + h * HD_;
            #pragma unroll
            for (int n = 0; n < 8; n++) {
                int col = n * 8 + cq;
                *(uint32_t*)&op0[col] = pack_half2(o[mt][n][0] * inv0, o[mt][n][1] * inv0);
                *(uint32_t*)&op1[col] = pack_half2(o[mt][n][2] * inv1, o[mt][n][3] * inv1);
            }
        }
    }
}

// ===========================================================================
extern "C" void kernel_launch(void* const* d_in, const int* in_sizes, int n_in,
                              void* d_out, int out_size) {
    (void)in_sizes; (void)n_in; (void)out_size;
    const float* X  = (const float*)d_in[0];
    const float* Wq = (const float*)d_in[1];
    const float* Wk = (const float*)d_in[2];
    const float* Wv = (const float*)d_in[3];
    const float* Wc = (const float*)d_in[4];
    const float* bc = (const float*)d_in[5];
    float* out = (float*)d_out;

    __half *xh, *wqkvh, *wch, *qh, *kh, *vh, *atth;
    cudaGetSymbolAddress((void**)&xh,    g_xh);
    cudaGetSymbolAddress((void**)&wqkvh, g_wqkvh);
    cudaGetSymbolAddress((void**)&wch,   g_wch);
    cudaGetSymbolAddress((void**)&qh,    g_qh);
    cudaGetSymbolAddress((void**)&kh,    g_kh);
    cudaGetSymbolAddress((void**)&vh,    g_vh);
    cudaGetSymbolAddress((void**)&atth,  g_atth);

    cudaFuncSetAttribute(attn_hmma_kernel,
                         cudaFuncAttributeMaxDynamicSharedMemorySize, SM_BYTES);

    const float QSCALE = 0.18033688011112042f;  // log2(e) / sqrt(HD_)

    f2h_kernel<<<(ROWS_ * D_) / 4 / 256, 256>>>(X, xh, ROWS_ * D_);
    f2h_w4_kernel<<<4 * 256, 256>>>(Wq, Wk, Wv, Wc, wqkvh, wch);

    hgemm_kernel<<<dim3(3 * D_ / PN, ROWS_ / PM), 256>>>(
        xh, wqkvh, qh, kh, vh, nullptr, nullptr, QSCALE);

    attn_hmma_kernel<<<dim3(S_ / BQ, B_ * H_), 256, SM_BYTES>>>(qh, kh, vh, atth);

    hgemm_kernel<<<dim3(D_ / PN, ROWS_ / PM), 256>>>(
        atth, wch, nullptr, nullptr, nullptr, out, bc, 1.0f);
}

// round 15
// speedup vs baseline: 1.0701x; 1.0701x over previous
#include <cuda_runtime.h>
#include <cuda_fp16.h>
#include <cstdint>
#include <math.h>

#define B_    2
#define S_    4096
#define D_    512
#define H_    8
#define HD_   64
#define ROWS_ (B_*S_)   // 8192

// fp16 scratch
__device__ __half g_xh   [(size_t)ROWS_*D_];
__device__ __half g_wqkvh[(size_t)3*D_*D_];
__device__ __half g_wch  [(size_t)D_*D_];
__device__ __half g_qh   [(size_t)B_*H_*S_*HD_];
__device__ __half g_kh   [(size_t)B_*H_*S_*HD_];
__device__ __half g_vh   [(size_t)B_*H_*S_*HD_];
__device__ __half g_atth [(size_t)B_*S_*D_];

__device__ __forceinline__ uint32_t smem_u32(const void* p) {
    uint32_t a;
    asm("{ .reg .u64 t; cvta.to.shared.u64 t, %1; cvt.u32.u64 %0, t; }" : "=r"(a) : "l"(p));
    return a;
}
__device__ __forceinline__ void mma16816(float* d, const uint32_t* a,
                                         const uint32_t* b, const float* c) {
    asm volatile(
        "mma.sync.aligned.m16n8k16.row.col.f32.f16.f16.f32 "
        "{%0,%1,%2,%3}, {%4,%5,%6,%7}, {%8,%9}, {%10,%11,%12,%13};"
        : "=f"(d[0]), "=f"(d[1]), "=f"(d[2]), "=f"(d[3])
        : "r"(a[0]), "r"(a[1]), "r"(a[2]), "r"(a[3]),
          "r"(b[0]), "r"(b[1]),
          "f"(c[0]), "f"(c[1]), "f"(c[2]), "f"(c[3]));
}
__device__ __forceinline__ uint32_t pack_half2(float a, float b) {
    __half2 h = __floats2half2_rn(a, b);
    return *(uint32_t*)&h;
}
// fp16x2 exp2 on MUFU: one op per 2 values
__device__ __forceinline__ uint32_t ex2_h2(uint32_t x) {
    uint32_t r; asm("ex2.approx.f16x2 %0, %1;" : "=r"(r) : "r"(x)); return r;
}

#define CP16(sa, gp) asm volatile("cp.async.cg.shared.global [%0], [%1], 16;" :: "r"(sa), "l"(gp))
#define CP_COMMIT()  asm volatile("cp.async.commit_group;")
#define CP_WAIT0()   asm volatile("cp.async.wait_group 0;")
#define BAR(id, cnt) asm volatile("bar.sync %0, %1;" :: "r"(id), "r"(cnt) : "memory")

#define LDSM4(r0,r1,r2,r3,a) \
    asm volatile("ldmatrix.sync.aligned.m8n8.x4.shared.b16 {%0,%1,%2,%3}, [%4];" \
        : "=r"(r0),"=r"(r1),"=r"(r2),"=r"(r3) : "r"(a))
#define LDSM4T(r0,r1,r2,r3,a) \
    asm volatile("ldmatrix.sync.aligned.m8n8.x4.trans.shared.b16 {%0,%1,%2,%3}, [%4];" \
        : "=r"(r0),"=r"(r1),"=r"(r2),"=r"(r3) : "r"(a))

// ===========================================================================
// fp32 -> fp16 conversions
// ===========================================================================
__global__ void f2h_kernel(const float* __restrict__ src, __half* __restrict__ dst, int n) {
    int i = (blockIdx.x * blockDim.x + threadIdx.x) * 4;
    if (i < n) {
        float4 v = *(const float4*)(src + i);
        *(uint2*)(dst + i) = make_uint2(pack_half2(v.x, v.y), pack_half2(v.z, v.w));
    }
}
__global__ void f2h_w4_kernel(const float* __restrict__ wq, const float* __restrict__ wk,
                              const float* __restrict__ wv, const float* __restrict__ wc,
                              __half* __restrict__ wqkv, __half* __restrict__ wcd) {
    const int sel = blockIdx.x >> 8;
    const int i = ((blockIdx.x & 255) * blockDim.x + threadIdx.x) * 4;
    const float* src = sel == 0 ? wq : (sel == 1 ? wk : (sel == 2 ? wv : wc));
    __half* dst = sel == 3 ? wcd : (wqkv + (size_t)sel * D_ * D_);
    float4 v = *(const float4*)(src + i);
    *(uint2*)(dst + i) = make_uint2(pack_half2(v.x, v.y), pack_half2(v.z, v.w));
}

// ===========================================================================
// Pipelined fp16 HMMA GEMM (unchanged)
// ===========================================================================
#define PM 128
#define PN 64
#define PKC 64
#define PPAD 72

__global__ void __launch_bounds__(256) hgemm_kernel(
    const __half* __restrict__ A, const __half* __restrict__ Wh,
    __half* __restrict__ qh, __half* __restrict__ kh, __half* __restrict__ vh,
    float* __restrict__ outF, const float* __restrict__ bias, float qscale) {
    __shared__ __half As[2][PM][PPAD];
    __shared__ __half Bs[2][PN][PPAD];
    const int tid = threadIdx.x;
    const int w = tid >> 5, lane = tid & 31;
    const int l4 = lane >> 2, cq = (lane & 3) * 2;
    const int bm0 = blockIdx.y * PM, bn0 = blockIdx.x * PN;
    const int mrow = (w >> 1) * 32, ncol = (w & 1) * 32;

    const uint32_t sbA = smem_u32(&As[0][0][0]);
    const uint32_t sbB = smem_u32(&Bs[0][0][0]);

    const int a_r = (lane & 7) + ((lane >> 3) & 1) * 8;
    const int a_c = (lane >> 4) * 8;
    const int b_r = lane & 7;
    const int b_c = (lane >> 3) * 8;

    auto loadAB = [&](int s, int kc) {
        #pragma unroll
        for (int i = 0; i < 4; i++) {
            int f = tid + i * 256;
            int r = f >> 3, c8 = f & 7;
            CP16(sbA + ((s * PM + r) * PPAD + c8 * 8) * 2,
                 A + (size_t)(bm0 + r) * D_ + kc * PKC + c8 * 8);
        }
        #pragma unroll
        for (int i = 0; i < 2; i++) {
            int f = tid + i * 256;
            int r = f >> 3, c8 = f & 7;
            CP16(sbB + ((s * PN + r) * PPAD + c8 * 8) * 2,
                 Wh + (size_t)(bn0 + r) * D_ + kc * PKC + c8 * 8);
        }
        CP_COMMIT();
    };

    float o[2][4][4];
    #pragma unroll
    for (int mt = 0; mt < 2; mt++)
        #pragma unroll
        for (int n = 0; n < 4; n++)
            #pragma unroll
            for (int j = 0; j < 4; j++) o[mt][n][j] = 0.f;

    loadAB(0, 0);

    const int NKC = D_ / PKC;
    for (int kc = 0; kc < NKC; kc++) {
        CP_WAIT0();
        __syncthreads();
        if (kc + 1 < NKC) loadAB((kc + 1) & 1, kc + 1);
        const int s = kc & 1;

        uint32_t af[2][4][4];
        #pragma unroll
        for (int mt = 0; mt < 2; mt++) {
            #pragma unroll
            for (int kk = 0; kk < 4; kk++) {
                uint32_t addr = sbA + ((s * PM + mrow + mt * 16 + a_r) * PPAD
                                       + kk * 16 + a_c) * 2;
                LDSM4(af[mt][kk][0], af[mt][kk][1], af[mt][kk][2], af[mt][kk][3], addr);
            }
        }
        #pragma unroll
        for (int n = 0; n < 4; n++) {
            uint32_t b0, b1, b2, b3, c0, c1, c2, c3;
            uint32_t addr = sbB + ((s * PN + ncol + n * 8 + b_r) * PPAD + b_c) * 2;
            LDSM4(b0, b1, b2, b3, addr);
            LDSM4(c0, c1, c2, c3, addr + 64);
            uint32_t bf0[2] = {b0, b1}, bf1[2] = {b2, b3};
            uint32_t bf2[2] = {c0, c1}, bf3[2] = {c2, c3};
            #pragma unroll
            for (int mt = 0; mt < 2; mt++) {
                mma16816(o[mt][n], af[mt][0], bf0, o[mt][n]);
                mma16816(o[mt][n], af[mt][1], bf1, o[mt][n]);
                mma16816(o[mt][n], af[mt][2], bf2, o[mt][n]);
                mma16816(o[mt][n], af[mt][3], bf3, o[mt][n]);
            }
        }
    }

    if (outF == nullptr) {
        const int sel = bn0 >> 9;
        __half* dst = sel == 0 ? qh : (sel == 1 ? kh : vh);
        const float sc = sel == 0 ? qscale : 1.f;
        #pragma unroll
        for (int mt = 0; mt < 2; mt++) {
            int r0 = bm0 + mrow + mt * 16 + l4;
            #pragma unroll
            for (int n = 0; n < 4; n++) {
                int cw = (bn0 + ncol + n * 8 + cq) & (D_ - 1);
                int h = cw >> 6, hd = cw & (HD_ - 1);
                #pragma unroll
                for (int rr = 0; rr < 2; rr++) {
                    int row = r0 + rr * 8;
                    int b = row >> 12, s2 = row & (S_ - 1);
                    uint32_t pv = pack_half2(o[mt][n][rr * 2] * sc,
                                             o[mt][n][rr * 2 + 1] * sc);
                    *(uint32_t*)&dst[((size_t)(b * H_ + h) * S_ + s2) * HD_ + hd] = pv;
                }
            }
        }
    } else {
        #pragma unroll
        for (int mt = 0; mt < 2; mt++) {
            int r0 = bm0 + mrow + mt * 16 + l4;
            #pragma unroll
            for (int n = 0; n < 4; n++) {
                int col = bn0 + ncol + n * 8 + cq;
                float b0 = bias[col], b1 = bias[col + 1];
                float* p0 = outF + (size_t)r0 * D_ + col;
                float* p1 = outF + (size_t)(r0 + 8) * D_ + col;
                p0[0] = o[mt][n][0] + b0; p0[1] = o[mt][n][1] + b1;
                p1[0] = o[mt][n][2] + b0; p1[1] = o[mt][n][3] + b1;
            }
        }
    }
}

// ===========================================================================
// Flash attention v6: round-12 structure (128-thread CTA, BQ=64, mt=2,
// 2 staggered groups of 2 warps, 2 CTAs/SM) + f16x2 softmax:
// ex2.approx.f16x2 halves MUFU ops; lsum via HADD2 chains + fp32 across tiles.
// ===========================================================================
#define BQ   64
#define BK   64
#define NT   (S_ / BK)          // 64 global tiles; 32 per group
#define NTL  (NT / 2)
#define QPAD 72
#define QS_H   (BQ * QPAD)              // 4608 halves
#define STG_H  (2 * BK * QPAD)          // 9216 halves (K + V)
#define KS_H(s) (QS_H + (s) * STG_H)    // stages 0..3 (A: 0,1  B: 2,3)
#define VS_H(s) (KS_H(s) + BK * QPAD)
#define MRG_H  KS_H(2)                  // merge buffer over group-B stages
#define SM_HALVES (QS_H + 4 * STG_H)    // 41472 halves
#define SM_BYTES  (SM_HALVES * 2)       // 82944

__global__ void __launch_bounds__(128, 2) attn_hmma_kernel(
    const __half* __restrict__ Qg, const __half* __restrict__ Kg,
    const __half* __restrict__ Vg, __half* __restrict__ att) {
    extern __shared__ __half sm[];
    const uint32_t sb = smem_u32(sm);

    const int tid = threadIdx.x;
    const int w = tid >> 5, lane = tid & 31;
    const int g  = w >> 1;                // warp group 0/1
    const int wg = w & 1;                 // warp within group (row half)
    const int tl = tid & 63;              // thread within group
    const int l4 = lane >> 2;
    const int cq = (lane & 3) * 2;
    const int bh = blockIdx.y;
    const int q0 = blockIdx.x * BQ;

    const __half* Qp = Qg + ((size_t)bh * S_ + q0) * HD_;
    const __half* Kp = Kg + (size_t)bh * S_ * HD_;
    const __half* Vp = Vg + (size_t)bh * S_ * HD_;

    auto issue_kv = [&](int gt, int s) {
        const __half* Kt = Kp + (size_t)gt * BK * HD_;
        const __half* Vt = Vp + (size_t)gt * BK * HD_;
        #pragma unroll
        for (int i = 0; i < 8; i++) {
            int f = tl + i * 64;
            int r = f >> 3, c8 = f & 7;
            CP16(sb + (KS_H(s) + r * QPAD + c8 * 8) * 2, Kt + (size_t)r * HD_ + c8 * 8);
            CP16(sb + (VS_H(s) + r * QPAD + c8 * 8) * 2, Vt + (size_t)r * HD_ + c8 * 8);
        }
        CP_COMMIT();
    };

    // ---- load Q tile ----
    #pragma unroll
    for (int i = 0; i < 4; i++) {
        int f = tid + i * 128;
        int r = f >> 3, c8 = f & 7;
        *(uint4*)&sm[r * QPAD + c8 * 8] = *(const uint4*)(Qp + (size_t)r * HD_ + c8 * 8);
    }

    issue_kv(g, g * 2);
    __syncthreads();   // Q visible

    // ---- Q fragments ----
    uint32_t qa[2][4][4];
    #pragma unroll
    for (int mt = 0; mt < 2; mt++) {
        const int row = wg * 32 + mt * 16 + l4;
        #pragma unroll
        for (int kk = 0; kk < 4; kk++) {
            qa[mt][kk][0] = *(uint32_t*)&sm[(row    ) * QPAD + kk * 16 + cq];
            qa[mt][kk][1] = *(uint32_t*)&sm[(row + 8) * QPAD + kk * 16 + cq];
            qa[mt][kk][2] = *(uint32_t*)&sm[(row    ) * QPAD + kk * 16 + 8 + cq];
            qa[mt][kk][3] = *(uint32_t*)&sm[(row + 8) * QPAD + kk * 16 + 8 + cq];
        }
    }

    float o[2][8][4];
    float lsum[2][2];
    #pragma unroll
    for (int mt = 0; mt < 2; mt++) {
        lsum[mt][0] = 0.f; lsum[mt][1] = 0.f;
        #pragma unroll
        for (int n = 0; n < 8; n++)
            #pragma unroll
            for (int j = 0; j < 4; j++) o[mt][n][j] = 0.f;
    }

    const int k_row8 = lane & 7;
    const int k_hdb  = (lane >> 3) * 8;
    const int v_key  = ((lane >> 3) & 1) * 8 + (lane & 7);
    const int v_hdb  = (lane >> 4) * 8;
    const int bar_id = g + 1;

    for (int t = 0; t < NTL; t++) {
        CP_WAIT0();
        BAR(bar_id, 64);

        if (t + 1 < NTL) issue_kv(2 * (t + 1) + g, g * 2 + ((t + 1) & 1));

        const uint32_t ks = sb + KS_H(g * 2 + (t & 1)) * 2;
        const uint32_t vs = sb + VS_H(g * 2 + (t & 1)) * 2;

        // ---- S = Q @ K^T ----
        float s[2][8][4];
        #pragma unroll
        for (int mt = 0; mt < 2; mt++)
            #pragma unroll
            for (int n = 0; n < 8; n++)
                #pragma unroll
                for (int j = 0; j < 4; j++) s[mt][n][j] = 0.f;

        #pragma unroll
        for (int n = 0; n < 8; n++) {
            uint32_t b0, b1, b2, b3, c0, c1, c2, c3;
            uint32_t a1 = ks + ((n * 8 + k_row8) * QPAD + k_hdb) * 2;
            LDSM4(b0, b1, b2, b3, a1);
            LDSM4(c0, c1, c2, c3, a1 + 64);
            uint32_t bk0[2] = {b0, b1}, bk1[2] = {b2, b3};
            uint32_t bk2[2] = {c0, c1}, bk3[2] = {c2, c3};
            #pragma unroll
            for (int mt = 0; mt < 2; mt++) {
                mma16816(s[mt][n], qa[mt][0], bk0, s[mt][n]);
                mma16816(s[mt][n], qa[mt][1], bk1, s[mt][n]);
                mma16816(s[mt][n], qa[mt][2], bk2, s[mt][n]);
                mma16816(s[mt][n], qa[mt][3], bk3, s[mt][n]);
            }
        }

        // ---- softmax: pack to f16x2 first, then ex2.approx.f16x2 (MUFU/2) ----
        uint32_t pa[2][4][4];
        #pragma unroll
        for (int mt = 0; mt < 2; mt++) {
            __half2 hacc0 = __floats2half2_rn(0.f, 0.f);
            __half2 hacc1 = __floats2half2_rn(0.f, 0.f);
            #pragma unroll
            for (int n = 0; n < 8; n++) {
                uint32_t p01 = ex2_h2(pack_half2(s[mt][n][0], s[mt][n][1]));
                uint32_t p23 = ex2_h2(pack_half2(s[mt][n][2], s[mt][n][3]));
                hacc0 = __hadd2(hacc0, *(__half2*)&p01);
                hacc1 = __hadd2(hacc1, *(__half2*)&p23);
                int j = n >> 1;
                if ((n & 1) == 0) {
                    pa[mt][j][0] = p01;
                    pa[mt][j][1] = p23;
                } else {
                    pa[mt][j][2] = p01;
                    pa[mt][j][3] = p23;
                }
            }
            lsum[mt][0] += __low2float(hacc0) + __high2float(hacc0);
            lsum[mt][1] += __low2float(hacc1) + __high2float(hacc1);
        }

        // ---- O += P @ V ----
        #pragma unroll
        for (int np = 0; np < 4; np++) {
            #pragma unroll
            for (int j = 0; j < 4; j++) {
                uint32_t v0, v1, v2, v3;
                uint32_t av = vs + ((j * 16 + v_key) * QPAD + np * 16 + v_hdb) * 2;
                LDSM4T(v0, v1, v2, v3, av);
                uint32_t bv0[2] = {v0, v1}, bv1[2] = {v2, v3};
                #pragma unroll
                for (int mt = 0; mt < 2; mt++) {
                    mma16816(o[mt][2 * np],     pa[mt][j], bv0, o[mt][2 * np]);
                    mma16816(o[mt][2 * np + 1], pa[mt][j], bv1, o[mt][2 * np + 1]);
                }
            }
        }
    }

    // ---- merge group B partials into group A ----
    float* mo = (float*)(sm + MRG_H);              // [2 warps][32 lanes][64]
    float* ml = mo + 2 * 32 * 64;                  // [2 warps][32 lanes][4]
    if (g == 1) {
        const int idx = wg * 32 + lane;
        #pragma unroll
        for (int mt = 0; mt < 2; mt++)
            #pragma unroll
            for (int n = 0; n < 8; n++)
                #pragma unroll
                for (int j = 0; j < 4; j++)
                    mo[idx * 64 + mt * 32 + n * 4 + j] = o[mt][n][j];
        #pragma unroll
        for (int mt = 0; mt < 2; mt++) {
            ml[idx * 4 + mt * 2]     = lsum[mt][0];
            ml[idx * 4 + mt * 2 + 1] = lsum[mt][1];
        }
    }
    __syncthreads();
    if (g == 0) {
        const int idx = wg * 32 + lane;
        #pragma unroll
        for (int mt = 0; mt < 2; mt++) {
            #pragma unroll
            for (int n = 0; n < 8; n++)
                #pragma unroll
                for (int j = 0; j < 4; j++)
                    o[mt][n][j] += mo[idx * 64 + mt * 32 + n * 4 + j];
            lsum[mt][0] += ml[idx * 4 + mt * 2];
            lsum[mt][1] += ml[idx * 4 + mt * 2 + 1];
        }

        #pragma unroll
        for (int mt = 0; mt < 2; mt++)
            #pragma unroll
            for (int hh = 0; hh < 2; hh++) {
                float v = lsum[mt][hh];
                v += __shfl_xor_sync(0xffffffffu, v, 1);
                v += __shfl_xor_sync(0xffffffffu, v, 2);
                lsum[mt][hh] = v;
            }

        const int b = bh >> 3, h = bh & 7;
        #pragma unroll
        for (int mt = 0; mt < 2; mt++) {
            const int row = q0 + wg * 32 + mt * 16 + l4;
            const float inv0 = 1.f / lsum[mt][0];
            const float inv1 = 1.f / lsum[mt][1];
            __half* op0 = att + ((size_t)(b * S_ + row    )) * D_ + h * HD_;
            __half* op1 = att + ((size_t)(b * S_ + row + 8)) * D_ + h * HD_;
            #pragma unroll
            for (int n = 0; n < 8; n++) {
                int col = n * 8 + cq;
                *(uint32_t*)&op0[col] = pack_half2(o[mt][n][0] * inv0, o[mt][n][1] * inv0);
                *(uint32_t*)&op1[col] = pack_half2(o[mt][n][2] * inv1, o[mt][n][3] * inv1);
            }
        }
    }
}

// ===========================================================================
extern "C" void kernel_launch(void* const* d_in, const int* in_sizes, int n_in,
                              void* d_out, int out_size) {
    (void)in_sizes; (void)n_in; (void)out_size;
    const float* X  = (const float*)d_in[0];
    const float* Wq = (const float*)d_in[1];
    const float* Wk = (const float*)d_in[2];
    const float* Wv = (const float*)d_in[3];
    const float* Wc = (const float*)d_in[4];
    const float* bc = (const float*)d_in[5];
    float* out = (float*)d_out;

    __half *xh, *wqkvh, *wch, *qh, *kh, *vh, *atth;
    cudaGetSymbolAddress((void**)&xh,    g_xh);
    cudaGetSymbolAddress((void**)&wqkvh, g_wqkvh);
    cudaGetSymbolAddress((void**)&wch,   g_wch);
    cudaGetSymbolAddress((void**)&qh,    g_qh);
    cudaGetSymbolAddress((void**)&kh,    g_kh);
    cudaGetSymbolAddress((void**)&vh,    g_vh);
    cudaGetSymbolAddress((void**)&atth,  g_atth);

    cudaFuncSetAttribute(attn_hmma_kernel,
                         cudaFuncAttributeMaxDynamicSharedMemorySize, SM_BYTES);

    const float QSCALE = 0.18033688011112042f;  // log2(e) / sqrt(HD_)

    f2h_kernel<<<(ROWS_ * D_) / 4 / 256, 256>>>(X, xh, ROWS_ * D_);
    f2h_w4_kernel<<<4 * 256, 256>>>(Wq, Wk, Wv, Wc, wqkvh, wch);

    hgemm_kernel<<<dim3(3 * D_ / PN, ROWS_ / PM), 256>>>(
        xh, wqkvh, qh, kh, vh, nullptr, nullptr, QSCALE);

    attn_hmma_kernel<<<dim3(S_ / BQ, B_ * H_), 128, SM_BYTES>>>(qh, kh, vh, atth);

    hgemm_kernel<<<dim3(D_ / PN, ROWS_ / PM), 256>>>(
        atth, wch, nullptr, nullptr, nullptr, out, bc, 1.0f);
}